// round 3
// baseline (speedup 1.0000x reference)
#include <cuda_runtime.h>

// out[b,j] = input2[b,j] * sum_i input1[b,i] * w2[i,j],  w2 = weights.sum(axis=2)
// B=16384, I=64, J=2048, K=64. All fp32.

#define B_DIM 16384
#define I_DIM 64
#define J_DIM 2048
#define K_DIM 64

// Scratch for K-reduced weights (allocation-free: __device__ global).
__device__ float g_w2[I_DIM * J_DIM];

// ---------------------------------------------------------------------------
// Kernel 1: w2[i,j] = sum_k weights[i,j,k]. One warp per (i,j) row of 64.
// ---------------------------------------------------------------------------
__global__ void reduce_w_kernel(const float* __restrict__ w) {
    int gw   = (blockIdx.x * blockDim.x + threadIdx.x) >> 5;  // row in [0, I*J)
    int lane = threadIdx.x & 31;
    const float* p = w + (size_t)gw * K_DIM;
    float s = p[lane] + p[lane + 32];
    #pragma unroll
    for (int o = 16; o > 0; o >>= 1)
        s += __shfl_down_sync(0xffffffffu, s, o);
    if (lane == 0) g_w2[gw] = s;
}

// ---------------------------------------------------------------------------
// Kernel 2: fused GEMM (x1 @ w2) * x2 via packed fp32x2 FMA (FFMA2).
// Tile 128(B) x 128(J), K=64 fully resident. 256 threads, 8x8 outputs/thread.
// x1 tile stored duplicated in smem as x1d[i][b] = {v,v} (f32x2), stride 130.
// ---------------------------------------------------------------------------
__device__ __forceinline__ unsigned long long ffma2(unsigned long long a,
                                                    unsigned long long b,
                                                    unsigned long long c) {
    unsigned long long d;
    asm("fma.rn.f32x2 %0, %1, %2, %3;" : "=l"(d) : "l"(a), "l"(b), "l"(c));
    return d;
}

#define BM 128
#define BN 128
#define X1_STRIDE 130   // ull per x1d row: even (16B LDS.128 align), 130 mod 16 != 0 padding

__global__ void __launch_bounds__(256, 2)
gemm_mul_kernel(const float* __restrict__ x1,
                const float* __restrict__ x2,
                float* __restrict__ out) {
    extern __shared__ char smem_raw[];
    float* w2s = (float*)smem_raw;                              // [64][128] fp32
    unsigned long long* x1d =
        (unsigned long long*)(smem_raw + I_DIM * BN * 4);       // [64][130] f32x2, x1d[i][b]={v,v}

    const int tid = threadIdx.x;
    const int tx  = tid & 15;     // j direction (16)
    const int ty  = tid >> 4;     // b direction (16); warp spans ty in {2t, 2t+1}
    const int j0  = blockIdx.x * BN;
    const int b0  = blockIdx.y * BM;

    // ---- Load w2 tile: [64 x 128], coalesced float4 ----
    #pragma unroll
    for (int k = 0; k < 8; k++) {
        int idx4 = tid + k * 256;           // 2048 float4 total
        int i    = idx4 >> 5;               // 32 float4 per row
        int c4   = idx4 & 31;
        float4 v = *(const float4*)(&g_w2[(size_t)i * J_DIM + j0 + c4 * 4]);
        *(float4*)(&w2s[i * BN + c4 * 4]) = v;
    }
    // ---- Load x1 tile, duplicated pairs: x1d[i][b] = {v,v} ----
    // b fast across lanes -> STS.64 at the 2-phase floor (no extra conflicts).
    #pragma unroll
    for (int k = 0; k < 8; k++) {
        int idx4 = tid + k * 256;           // 2048 float4 (128 b x 16 i-groups)
        int b    = idx4 & 127;
        int i4   = idx4 >> 7;               // 0..15
        float4 v = *(const float4*)(&x1[(size_t)(b0 + b) * I_DIM + i4 * 4]);
        x1d[(i4 * 4 + 0) * X1_STRIDE + b] =
            ((unsigned long long)__float_as_uint(v.x) << 32) | __float_as_uint(v.x);
        x1d[(i4 * 4 + 1) * X1_STRIDE + b] =
            ((unsigned long long)__float_as_uint(v.y) << 32) | __float_as_uint(v.y);
        x1d[(i4 * 4 + 2) * X1_STRIDE + b] =
            ((unsigned long long)__float_as_uint(v.z) << 32) | __float_as_uint(v.z);
        x1d[(i4 * 4 + 3) * X1_STRIDE + b] =
            ((unsigned long long)__float_as_uint(v.w) << 32) | __float_as_uint(v.w);
    }
    __syncthreads();

    // ---- Mainloop: 64 K-steps, 8 b-rows x 4 j-pairs per thread ----
    unsigned long long acc[8][4];
    #pragma unroll
    for (int r = 0; r < 8; r++)
        #pragma unroll
        for (int p = 0; p < 4; p++) acc[r][p] = 0ull;   // {0.0f, 0.0f}

    const int arow = ty * 8;      // b offset of this thread (16B-aligned in x1d row)
    const int bcol = tx * 8;      // j offset of this thread

    #pragma unroll 4
    for (int i = 0; i < I_DIM; i++) {
        // a: 8 duplicated pairs, contiguous -> 4x LDS.128, conflict-free
        ulonglong2 a01 = *(const ulonglong2*)(&x1d[i * X1_STRIDE + arow + 0]);
        ulonglong2 a23 = *(const ulonglong2*)(&x1d[i * X1_STRIDE + arow + 2]);
        ulonglong2 a45 = *(const ulonglong2*)(&x1d[i * X1_STRIDE + arow + 4]);
        ulonglong2 a67 = *(const ulonglong2*)(&x1d[i * X1_STRIDE + arow + 6]);
        unsigned long long a[8] = {a01.x, a01.y, a23.x, a23.y,
                                   a45.x, a45.y, a67.x, a67.y};
        // b: 8 w2 values as 4 j-pairs -> 2x LDS.128
        ulonglong2 b01 = *(const ulonglong2*)(&w2s[i * BN + bcol]);
        ulonglong2 b23 = *(const ulonglong2*)(&w2s[i * BN + bcol + 4]);
        unsigned long long bb[4] = {b01.x, b01.y, b23.x, b23.y};
        #pragma unroll
        for (int r = 0; r < 8; r++)
            #pragma unroll
            for (int p = 0; p < 4; p++)
                acc[r][p] = ffma2(a[r], bb[p], acc[r][p]);
    }

    // ---- Epilogue: multiply by x2, float4 stores ----
    #pragma unroll
    for (int r = 0; r < 8; r++) {
        size_t row = (size_t)(b0 + arow + r) * J_DIM + j0 + bcol;
        float4 xa = *(const float4*)(&x2[row]);
        float4 xb = *(const float4*)(&x2[row + 4]);

        float lo0 = __uint_as_float((unsigned)acc[r][0]);
        float hi0 = __uint_as_float((unsigned)(acc[r][0] >> 32));
        float lo1 = __uint_as_float((unsigned)acc[r][1]);
        float hi1 = __uint_as_float((unsigned)(acc[r][1] >> 32));
        float lo2 = __uint_as_float((unsigned)acc[r][2]);
        float hi2 = __uint_as_float((unsigned)(acc[r][2] >> 32));
        float lo3 = __uint_as_float((unsigned)acc[r][3]);
        float hi3 = __uint_as_float((unsigned)(acc[r][3] >> 32));

        float4 o0 = make_float4(lo0 * xa.x, hi0 * xa.y, lo1 * xa.z, hi1 * xa.w);
        float4 o1 = make_float4(lo2 * xb.x, hi2 * xb.y, lo3 * xb.z, hi3 * xb.w);
        *(float4*)(&out[row])     = o0;
        *(float4*)(&out[row + 4]) = o1;
    }
}

// ---------------------------------------------------------------------------
extern "C" void kernel_launch(void* const* d_in, const int* in_sizes, int n_in,
                              void* d_out, int out_size) {
    const float* x1 = (const float*)d_in[0];  // (B, I)
    const float* x2 = (const float*)d_in[1];  // (B, J)
    const float* w  = (const float*)d_in[2];  // (I, J, K)
    float* out      = (float*)d_out;          // (B, J)

    // Kernel 1: K-reduction of weights. 131072 rows, 1 warp each, 8 warps/block.
    reduce_w_kernel<<<(I_DIM * J_DIM) / 8, 256>>>(w);

    // Kernel 2: fused GEMM + elementwise multiply.
    const int smem_bytes = I_DIM * BN * 4                 // w2s: 32768
                         + I_DIM * X1_STRIDE * 8;         // x1d: 66560
    cudaFuncSetAttribute(gemm_mul_kernel,
                         cudaFuncAttributeMaxDynamicSharedMemorySize, smem_bytes);
    dim3 grid(J_DIM / BN, B_DIM / BM);   // (16, 128)
    gemm_mul_kernel<<<grid, 256, smem_bytes>>>(x1, x2, out);
}